// round 4
// baseline (speedup 1.0000x reference)
#include <cuda_runtime.h>
#include <math.h>

// ---------------------------------------------------------------------------
// GRNNTransformGated: binary-tree GRNN, B=1024, L=10, H=128, FEAT=7.
// Round 2: packed fp32 (fma.rn.f32x2) everywhere, 512 threads/block,
// software-pipelined weight staging.
// ---------------------------------------------------------------------------

#define TM   64
#define NT   512
#define SAS  388          // row stride (floats) for 64x384 activation arrays; mult of 4 for float4
#define SWS  132          // row stride (floats) for 32x128 weight staging tile

__device__ float g_embA[524288 * 128];
__device__ float g_embB[524288 * 128];

typedef unsigned long long u64;

__device__ __forceinline__ u64 pk2(float x, float y) {
    u64 r; asm("mov.b64 %0,{%1,%2};" : "=l"(r) : "f"(x), "f"(y)); return r;
}
__device__ __forceinline__ float2 up2(u64 v) {
    float2 f; asm("mov.b64 {%0,%1},%2;" : "=f"(f.x), "=f"(f.y) : "l"(v)); return f;
}
#define FMA2(c, a, b) asm("fma.rn.f32x2 %0,%1,%2,%0;" : "+l"(c) : "l"(a), "l"(b))

__device__ __forceinline__ float conv3(float x, float cw, float cb) {
    x = fmaxf(fmaf(cw, x, cb), 0.0f);
    x = fmaxf(fmaf(cw, x, cb), 0.0f);
    x = fmaxf(fmaf(cw, x, cb), 0.0f);
    return x;
}

// ---------------------------------------------------------------------------
// Leaf level (j=9): emb = conv3(contents @ W_u + b_u).
// ---------------------------------------------------------------------------
__global__ __launch_bounds__(256, 1)
void leaf_kernel(const float* __restrict__ contents,
                 const float* __restrict__ W_u, const float* __restrict__ b_u,
                 const float* __restrict__ cwp, const float* __restrict__ cbp,
                 float* __restrict__ emb)
{
    const int node = blockIdx.x * 2 + (threadIdx.x >> 7);
    const int h    = threadIdx.x & 127;
    const float cw = cwp[0], cb = cbp[0];
    const float* c = contents + (long long)node * 7;
    float acc = b_u[h];
#pragma unroll
    for (int f = 0; f < 7; ++f)
        acc = fmaf(c[f], W_u[f * 128 + h], acc);
    emb[(long long)node * 128 + h] = conv3(acc, cw, cb);
}

// ---------------------------------------------------------------------------
// Inner level kernel (j < 9). 512 threads, 64 nodes per block.
// Per thread: 2 rows (r0,r1) x 8 columns.
// ---------------------------------------------------------------------------
__global__ __launch_bounds__(NT, 1)
void level_kernel(const float* __restrict__ contents,
                  const float* __restrict__ emb_prev,
                  float* __restrict__ emb_out,
                  const float* __restrict__ W_u, const float* __restrict__ b_u,
                  const float* __restrict__ W_r, const float* __restrict__ b_r,
                  const float* __restrict__ W_h, const float* __restrict__ b_h,
                  const float* __restrict__ W_z, const float* __restrict__ b_z,
                  const float* __restrict__ cwp, const float* __restrict__ cbp)
{
    extern __shared__ float sm[];
    float* s_hhu = sm;                       // [64][SAS]  cols 0..127 hL, 128..255 hR, 256..383 u
    float* s_a   = sm + TM * SAS;            // [64][SAS]  A, later HH in cols 0..127
    float* s_w   = sm + 2 * TM * SAS;        // [32][SWS]

    const int tid = threadIdx.x;
    const int tc  = tid & 15;                // column-thread 0..15
    const int tr  = tid >> 4;                // row-thread 0..31
    const int r0  = tr * 2, r1 = r0 + 1;
    const int m0  = blockIdx.x * TM;
    const float cw = cwp[0], cb = cbp[0];

    // ---- load h_L | h_R : contiguous 64x256 slab of emb_prev ----
    {
        const float4* src = (const float4*)(emb_prev + (long long)(2 * m0) * 128);
        for (int q = tid; q < TM * 64; q += NT) {
            const int row = q >> 6, c4 = q & 63;
            float4 v = src[q];
            float* d = s_hhu + row * SAS + c4 * 4;
            d[0] = v.x; d[1] = v.y; d[2] = v.z; d[3] = v.w;
        }
    }
    // ---- u = conv3(contents @ W_u + b_u) into cols 256..383 ----
#pragma unroll
    for (int i = 0; i < 2; ++i) {
        const int row = r0 + i;
        const float* c = contents + (long long)(m0 + row) * 7;
        float cf[7];
#pragma unroll
        for (int f = 0; f < 7; ++f) cf[f] = c[f];
#pragma unroll
        for (int jj = 0; jj < 8; ++jj) {
            const int h = tc * 8 + jj;
            float acc = b_u[h];
#pragma unroll
            for (int f = 0; f < 7; ++f)
                acc = fmaf(cf[f], W_u[f * 128 + h], acc);
            s_hhu[row * SAS + 256 + h] = conv3(acc, cw, cb);
        }
    }
    __syncthreads();

    // ================= R stage: A = sigmoid(HHU@W_r + b_r) * HHU ============
#pragma unroll 1
    for (int n0 = 0; n0 < 384; n0 += 128) {
        u64 acc[2][4];
#pragma unroll
        for (int jp = 0; jp < 4; ++jp) {
            float2 b = *(const float2*)(b_r + n0 + tc * 8 + jp * 2);
            u64 bp = pk2(b.x, b.y);
            acc[0][jp] = bp; acc[1][jp] = bp;
        }
        float4 pf0, pf1;
        {   // prefetch tile k0=0
            int id = tid, kk = id >> 5, c4 = id & 31;
            pf0 = *(const float4*)(W_r + (long long)kk * 384 + n0 + c4 * 4);
            id = tid + NT; kk = id >> 5; c4 = id & 31;
            pf1 = *(const float4*)(W_r + (long long)kk * 384 + n0 + c4 * 4);
        }
#pragma unroll 1
        for (int k0 = 0; k0 < 384; k0 += 32) {
            __syncthreads();
            {
                int id = tid, kk = id >> 5, c4 = id & 31;
                *(float4*)(s_w + kk * SWS + c4 * 4) = pf0;
                id = tid + NT; kk = id >> 5; c4 = id & 31;
                *(float4*)(s_w + kk * SWS + c4 * 4) = pf1;
            }
            __syncthreads();
            if (k0 + 32 < 384) {
                int id = tid, kk = id >> 5, c4 = id & 31;
                pf0 = *(const float4*)(W_r + (long long)(k0 + 32 + kk) * 384 + n0 + c4 * 4);
                id = tid + NT; kk = id >> 5; c4 = id & 31;
                pf1 = *(const float4*)(W_r + (long long)(k0 + 32 + kk) * 384 + n0 + c4 * 4);
            }
#pragma unroll
            for (int kk = 0; kk < 32; kk += 4) {
                float4 av0 = *(const float4*)(s_hhu + r0 * SAS + k0 + kk);
                float4 av1 = *(const float4*)(s_hhu + r1 * SAS + k0 + kk);
#pragma unroll
                for (int t = 0; t < 4; ++t) {
                    const float a0 = ((const float*)&av0)[t];
                    const float a1 = ((const float*)&av1)[t];
                    const u64 ap0 = pk2(a0, a0), ap1 = pk2(a1, a1);
                    const ulonglong2* wp = (const ulonglong2*)(s_w + (kk + t) * SWS + tc * 8);
                    const ulonglong2 wA = wp[0], wB = wp[1];
                    FMA2(acc[0][0], ap0, wA.x); FMA2(acc[0][1], ap0, wA.y);
                    FMA2(acc[0][2], ap0, wB.x); FMA2(acc[0][3], ap0, wB.y);
                    FMA2(acc[1][0], ap1, wA.x); FMA2(acc[1][1], ap1, wA.y);
                    FMA2(acc[1][2], ap1, wB.x); FMA2(acc[1][3], ap1, wB.y);
                }
            }
        }
        // epilogue: sigmoid * HHU -> s_a
#pragma unroll
        for (int i = 0; i < 2; ++i) {
            const int row = r0 + i;
#pragma unroll
            for (int jp = 0; jp < 4; ++jp) {
                float2 v = up2(acc[i][jp]);
                const int col = n0 + tc * 8 + jp * 2;
                const float ra = 1.0f / (1.0f + __expf(-v.x));
                const float rb = 1.0f / (1.0f + __expf(-v.y));
                s_a[row * SAS + col]     = ra * s_hhu[row * SAS + col];
                s_a[row * SAS + col + 1] = rb * s_hhu[row * SAS + col + 1];
            }
        }
    }
    __syncthreads();   // full A ready

    // ================= H stage: HH = conv3(A @ W_h + b_h) ===================
    {
        u64 acc[2][4];
#pragma unroll
        for (int jp = 0; jp < 4; ++jp) {
            float2 b = *(const float2*)(b_h + tc * 8 + jp * 2);
            u64 bp = pk2(b.x, b.y);
            acc[0][jp] = bp; acc[1][jp] = bp;
        }
        float4 pf0, pf1;
        {
            int id = tid, kk = id >> 5, c4 = id & 31;
            pf0 = *(const float4*)(W_h + (long long)kk * 128 + c4 * 4);
            id = tid + NT; kk = id >> 5; c4 = id & 31;
            pf1 = *(const float4*)(W_h + (long long)kk * 128 + c4 * 4);
        }
#pragma unroll 1
        for (int k0 = 0; k0 < 384; k0 += 32) {
            __syncthreads();
            {
                int id = tid, kk = id >> 5, c4 = id & 31;
                *(float4*)(s_w + kk * SWS + c4 * 4) = pf0;
                id = tid + NT; kk = id >> 5; c4 = id & 31;
                *(float4*)(s_w + kk * SWS + c4 * 4) = pf1;
            }
            __syncthreads();
            if (k0 + 32 < 384) {
                int id = tid, kk = id >> 5, c4 = id & 31;
                pf0 = *(const float4*)(W_h + (long long)(k0 + 32 + kk) * 128 + c4 * 4);
                id = tid + NT; kk = id >> 5; c4 = id & 31;
                pf1 = *(const float4*)(W_h + (long long)(k0 + 32 + kk) * 128 + c4 * 4);
            }
#pragma unroll
            for (int kk = 0; kk < 32; kk += 4) {
                float4 av0 = *(const float4*)(s_a + r0 * SAS + k0 + kk);
                float4 av1 = *(const float4*)(s_a + r1 * SAS + k0 + kk);
#pragma unroll
                for (int t = 0; t < 4; ++t) {
                    const float a0 = ((const float*)&av0)[t];
                    const float a1 = ((const float*)&av1)[t];
                    const u64 ap0 = pk2(a0, a0), ap1 = pk2(a1, a1);
                    const ulonglong2* wp = (const ulonglong2*)(s_w + (kk + t) * SWS + tc * 8);
                    const ulonglong2 wA = wp[0], wB = wp[1];
                    FMA2(acc[0][0], ap0, wA.x); FMA2(acc[0][1], ap0, wA.y);
                    FMA2(acc[0][2], ap0, wB.x); FMA2(acc[0][3], ap0, wB.y);
                    FMA2(acc[1][0], ap1, wA.x); FMA2(acc[1][1], ap1, wA.y);
                    FMA2(acc[1][2], ap1, wB.x); FMA2(acc[1][3], ap1, wB.y);
                }
            }
        }
        // overwrite s_a[:, 0:128] with HH (last k-tile reads only cols 352..383)
#pragma unroll
        for (int i = 0; i < 2; ++i) {
            const int row = r0 + i;
#pragma unroll
            for (int jp = 0; jp < 4; ++jp) {
                float2 v = up2(acc[i][jp]);
                const int col = tc * 8 + jp * 2;
                s_a[row * SAS + col]     = conv3(v.x, cw, cb);
                s_a[row * SAS + col + 1] = conv3(v.y, cw, cb);
            }
        }
    }
    __syncthreads();

    // ================= Z stage + gated softmax output ========================
    // Per fc: 32 features x 4 gates packed into 128 cols of s_w as [kk][g*32 + lc].
    // Thread owns feature pair (tc*2, tc*2+1), all 4 gates; pairs packed over feats.
#pragma unroll 1
    for (int fc = 0; fc < 4; ++fc) {
        u64 acc[2][4];   // [row][gate], f32x2 over the two features
#pragma unroll
        for (int g = 0; g < 4; ++g) {
            float2 b = *(const float2*)(b_z + g * 128 + fc * 32 + tc * 2);
            u64 bp = pk2(b.x, b.y);
            acc[0][g] = bp; acc[1][g] = bp;
        }
        float4 pf0, pf1;
        {
            int id = tid, kk = id >> 5, p = id & 31;
            int g = p >> 3, lc = (p & 7) * 4;
            pf0 = *(const float4*)(W_z + (long long)kk * 512 + g * 128 + fc * 32 + lc);
            id = tid + NT; kk = id >> 5; p = id & 31; g = p >> 3; lc = (p & 7) * 4;
            pf1 = *(const float4*)(W_z + (long long)kk * 512 + g * 128 + fc * 32 + lc);
        }
#pragma unroll 1
        for (int k0 = 0; k0 < 512; k0 += 32) {
            __syncthreads();
            {
                int id = tid, kk = id >> 5, p = id & 31;
                int g = p >> 3, lc = (p & 7) * 4;
                *(float4*)(s_w + kk * SWS + g * 32 + lc) = pf0;
                id = tid + NT; kk = id >> 5; p = id & 31; g = p >> 3; lc = (p & 7) * 4;
                *(float4*)(s_w + kk * SWS + g * 32 + lc) = pf1;
            }
            __syncthreads();
            if (k0 + 32 < 512) {
                int id = tid, kk = id >> 5, p = id & 31;
                int g = p >> 3, lc = (p & 7) * 4;
                pf0 = *(const float4*)(W_z + (long long)(k0 + 32 + kk) * 512 + g * 128 + fc * 32 + lc);
                id = tid + NT; kk = id >> 5; p = id & 31; g = p >> 3; lc = (p & 7) * 4;
                pf1 = *(const float4*)(W_z + (long long)(k0 + 32 + kk) * 512 + g * 128 + fc * 32 + lc);
            }
            const float* ab = (k0 < 128) ? (s_a + k0) : (s_hhu + (k0 - 128));
#pragma unroll
            for (int kk = 0; kk < 32; kk += 4) {
                float4 av0 = *(const float4*)(ab + r0 * SAS + kk);
                float4 av1 = *(const float4*)(ab + r1 * SAS + kk);
#pragma unroll
                for (int t = 0; t < 4; ++t) {
                    const float a0 = ((const float*)&av0)[t];
                    const float a1 = ((const float*)&av1)[t];
                    const u64 ap0 = pk2(a0, a0), ap1 = pk2(a1, a1);
                    const float* wrow = s_w + (kk + t) * SWS + tc * 2;
                    const u64 w0 = *(const u64*)(wrow);
                    const u64 w1 = *(const u64*)(wrow + 32);
                    const u64 w2 = *(const u64*)(wrow + 64);
                    const u64 w3 = *(const u64*)(wrow + 96);
                    FMA2(acc[0][0], ap0, w0); FMA2(acc[0][1], ap0, w1);
                    FMA2(acc[0][2], ap0, w2); FMA2(acc[0][3], ap0, w3);
                    FMA2(acc[1][0], ap1, w0); FMA2(acc[1][1], ap1, w1);
                    FMA2(acc[1][2], ap1, w2); FMA2(acc[1][3], ap1, w3);
                }
            }
        }
        // epilogue: softmax over gates, combine, write out
#pragma unroll
        for (int i = 0; i < 2; ++i) {
            const int row = r0 + i;
            float2 z[4];
#pragma unroll
            for (int g = 0; g < 4; ++g) z[g] = up2(acc[i][g]);
#pragma unroll
            for (int f = 0; f < 2; ++f) {
                const float z0 = f ? z[0].y : z[0].x;
                const float z1 = f ? z[1].y : z[1].x;
                const float z2 = f ? z[2].y : z[2].x;
                const float z3 = f ? z[3].y : z[3].x;
                const float mx = fmaxf(fmaxf(z0, z1), fmaxf(z2, z3));
                const float e0 = __expf(z0 - mx), e1 = __expf(z1 - mx);
                const float e2 = __expf(z2 - mx), e3 = __expf(z3 - mx);
                const float inv = 1.0f / (e0 + e1 + e2 + e3);
                const int c = fc * 32 + tc * 2 + f;
                const float hH = s_a[row * SAS + c];
                const float hL = s_hhu[row * SAS + c];
                const float hR = s_hhu[row * SAS + 128 + c];
                const float uu = s_hhu[row * SAS + 256 + c];
                emb_out[(long long)(m0 + row) * 128 + c] =
                    (e0 * hH + e1 * hL + e2 * hR + e3 * uu) * inv;
            }
        }
    }
}

// ---------------------------------------------------------------------------
// Host launcher
// ---------------------------------------------------------------------------
extern "C" void kernel_launch(void* const* d_in, const int* in_sizes, int n_in,
                              void* d_out, int out_size)
{
    const float* contents = (const float*)d_in[0];
    // d_in[1] = children (int32) — structurally [2i, 2i+1]; not needed.
    const float* W_u = (const float*)d_in[2];
    const float* b_u = (const float*)d_in[3];
    const float* W_h = (const float*)d_in[4];
    const float* b_h = (const float*)d_in[5];
    const float* W_z = (const float*)d_in[6];
    const float* b_z = (const float*)d_in[7];
    const float* W_r = (const float*)d_in[8];
    const float* b_r = (const float*)d_in[9];
    const float* cw  = (const float*)d_in[10];
    const float* cb  = (const float*)d_in[11];

    float *embA, *embB;
    cudaGetSymbolAddress((void**)&embA, g_embA);
    cudaGetSymbolAddress((void**)&embB, g_embB);

    const int smem = (2 * TM * SAS + 32 * SWS) * (int)sizeof(float);
    cudaFuncSetAttribute(level_kernel, cudaFuncAttributeMaxDynamicSharedMemorySize, smem);

    // Level 9 (leaves)
    {
        const long long off9 = 1024LL * ((1LL << 9) - 1);
        const int n9 = 1024 << 9;
        leaf_kernel<<<n9 / 2, 256>>>(contents + off9 * 7, W_u, b_u, cw, cb, embA);
    }

    const float* prev = embA;
    for (int j = 8; j >= 0; --j) {
        const long long off = 1024LL * ((1LL << j) - 1);
        const int n = 1024 << j;
        float* outp = (j == 0) ? (float*)d_out : ((prev == embA) ? embB : embA);
        level_kernel<<<n / TM, NT, smem>>>(
            contents + off * 7, prev, outp,
            W_u, b_u, W_r, b_r, W_h, b_h, W_z, b_z, cw, cb);
        prev = outp;
    }
}